// round 5
// baseline (speedup 1.0000x reference)
#include <cuda_runtime.h>
#include <cuda_fp16.h>

#define N_NODES 131072
#define KNBR    27
#define FIN     3
#define FOUT    32
#define EPS     1e-5f

// ---------------- scratch (static device arrays: no allocation) ----------------
__device__ __align__(16) __half g_h[(size_t)N_NODES * FOUT];   // 8 MB, fp16 h
__device__ __align__(16) float4 g_xp[N_NODES];                 // 2 MB, padded x

// ---------------- f32x2 packed-FMA helpers (PTX-only, sm_100+) -----------------
__device__ __forceinline__ void ffma2(unsigned long long& d,
                                      unsigned long long a,
                                      unsigned long long b) {
    asm volatile("fma.rn.f32x2 %0, %1, %2, %0;" : "+l"(d) : "l"(a), "l"(b));
}
__device__ __forceinline__ unsigned long long dup2(float x) {
    unsigned long long r;
    asm("mov.b64 %0, {%1, %1};" : "=l"(r) : "f"(x));
    return r;
}
union U64F2 { unsigned long long u; float2 f; };

// ---------------- kernel 0: pad x_feats rows to 16B ---------------------------
__global__ void pad_x_kernel(const float* __restrict__ x) {
    int n = blockIdx.x * blockDim.x + threadIdx.x;
    if (n < N_NODES) {
        float4 v;
        v.x = x[3 * (size_t)n];
        v.y = x[3 * (size_t)n + 1];
        v.z = x[3 * (size_t)n + 2];
        v.w = 0.f;
        g_xp[n] = v;
    }
}

// ---------------- kernel 1: h = silu(bn(gatherGEMM(x, w1))) -> fp16 -----------
__global__ __launch_bounds__(256) void stage1_kernel(
    const int*   __restrict__ nbr,
    const float* __restrict__ w1,
    const float* __restrict__ gamma1,
    const float* __restrict__ beta1,
    const float* __restrict__ mean1,
    const float* __restrict__ var1)
{
    __shared__ __align__(16) float wf[KNBR * FIN * FOUT];  // w1 * scale[o]
    __shared__ float ssc[FOUT];
    __shared__ float sb[FOUT];

    int tid = threadIdx.x;
    if (tid < FOUT) {
        float s = gamma1[tid] * rsqrtf(var1[tid] + EPS);
        ssc[tid] = s;
        sb[tid]  = beta1[tid] - mean1[tid] * s;
    }
    __syncthreads();
    for (int i = tid; i < KNBR * FIN * FOUT; i += 256)
        wf[i] = w1[i] * ssc[i & 31];
    __syncthreads();

    int n = blockIdx.x * 256 + tid;
    const int* nb = nbr + (size_t)n * KNBR;

    unsigned long long acc[16];
    #pragma unroll
    for (int j = 0; j < 16; j++) acc[j] = 0ull;

    #pragma unroll 1
    for (int k = 0; k < KNBR; k++) {
        int idx = nb[k];
        float4 xv = g_xp[idx];
        float xr[3] = {xv.x, xv.y, xv.z};
        #pragma unroll
        for (int f = 0; f < FIN; f++) {
            unsigned long long hf = dup2(xr[f]);
            const ulonglong2* wrow =
                reinterpret_cast<const ulonglong2*>(wf + (k * FIN + f) * FOUT);
            #pragma unroll
            for (int j = 0; j < 8; j++) {
                ulonglong2 w = wrow[j];
                ffma2(acc[2 * j],     hf, w.x);
                ffma2(acc[2 * j + 1], hf, w.y);
            }
        }
    }

    // bias + silu + fp16 store (4 x 16B stores)
    uint4* hp4 = reinterpret_cast<uint4*>(g_h + (size_t)n * FOUT);
    #pragma unroll
    for (int q = 0; q < 4; q++) {
        unsigned int u[4];
        #pragma unroll
        for (int p = 0; p < 4; p++) {
            int j = q * 4 + p;                 // half2 j = channels {2j, 2j+1}
            U64F2 uv; uv.u = acc[j];
            float a0 = uv.f.x + sb[2 * j];
            float a1 = uv.f.y + sb[2 * j + 1];
            a0 = a0 / (1.f + __expf(-a0));     // silu
            a1 = a1 / (1.f + __expf(-a1));
            __half2 hh = __floats2half2_rn(a0, a1);
            u[p] = *reinterpret_cast<unsigned int*>(&hh);
        }
        hp4[q] = make_uint4(u[0], u[1], u[2], u[3]);
    }
}

// ---------------- kernel 2: x_out = gatherGEMM(h, w2); out = x_out + mlp(z) ---
__device__ __forceinline__ void finish_node(
    int n, const unsigned long long* acc,
    const float* __restrict__ zf, const float* zw, const float* zb,
    float* __restrict__ out, size_t off2)
{
    float z0 = zf[3 * (size_t)n];
    float z1 = zf[3 * (size_t)n + 1];
    float z2 = zf[3 * (size_t)n + 2];

    float res[FOUT];
    #pragma unroll
    for (int j = 0; j < 16; j++) {
        U64F2 u; u.u = acc[j];
        res[2 * j]     = u.f.x;
        res[2 * j + 1] = u.f.y;
    }
    #pragma unroll
    for (int o = 0; o < FOUT; o++) {
        float z = fmaf(z0, zw[o], fmaf(z1, zw[FOUT + o],
                 fmaf(z2, zw[2 * FOUT + o], zb[o])));
        res[o] += fmaxf(z, 0.f);               // relu(bn(linear)) folded
    }

    float4* p1 = reinterpret_cast<float4*>(out + (size_t)n * FOUT);
    float4* p2 = reinterpret_cast<float4*>(out + off2 + (size_t)n * FOUT);
    #pragma unroll
    for (int j = 0; j < 8; j++) {
        float4 v = make_float4(res[4 * j], res[4 * j + 1],
                               res[4 * j + 2], res[4 * j + 3]);
        p1[j] = v;
        p2[j] = v;
    }
}

extern __shared__ float smemB[];  // [27*1024] w2 | [3*32] zw | [32] zb

__global__ __launch_bounds__(256, 1) void stage2_kernel(
    const int*   __restrict__ nbr,
    const float* __restrict__ w2,
    const float* __restrict__ zf,
    const float* __restrict__ mw,
    const float* __restrict__ mb,
    const float* __restrict__ mg,
    const float* __restrict__ mbeta,
    const float* __restrict__ mmean,
    const float* __restrict__ mvar,
    float* __restrict__ out, size_t off2)
{
    float* w2s = smemB;
    float* zw  = smemB + KNBR * FOUT * FOUT;   // 27648
    float* zb  = zw + FIN * FOUT;

    int tid = threadIdx.x;
    if (tid < FOUT) {
        float s = mg[tid] * rsqrtf(mvar[tid] + EPS);
        zb[tid] = (mb[tid] - mmean[tid]) * s + mbeta[tid];
        #pragma unroll
        for (int f = 0; f < FIN; f++)
            zw[f * FOUT + tid] = mw[f * FOUT + tid] * s;
    }
    {   // cooperative w2 -> smem (110 KB)
        const float4* src = reinterpret_cast<const float4*>(w2);
        float4* dst = reinterpret_cast<float4*>(w2s);
        for (int i = tid; i < KNBR * FOUT * FOUT / 4; i += 256) dst[i] = src[i];
    }
    __syncthreads();

    int n0 = blockIdx.x * 512 + tid;           // 2 nodes / thread
    int n1 = n0 + 256;
    const int* nb0 = nbr + (size_t)n0 * KNBR;
    const int* nb1 = nbr + (size_t)n1 * KNBR;

    unsigned long long a0[16], a1[16];
    #pragma unroll
    for (int j = 0; j < 16; j++) { a0[j] = 0ull; a1[j] = 0ull; }

    const uint4* hbase = reinterpret_cast<const uint4*>(g_h);

    #pragma unroll 1
    for (int k = 0; k < KNBR; k++) {
        int i0 = nb0[k];
        int i1 = nb1[k];
        uint4 r0[4], r1[4];                    // fp16 rows, 64B each
        #pragma unroll
        for (int q = 0; q < 4; q++) {
            r0[q] = hbase[(size_t)i0 * 4 + q];
            r1[q] = hbase[(size_t)i1 * 4 + q];
        }
        const float* wk = w2s + k * FOUT * FOUT;

        #pragma unroll
        for (int q = 0; q < 4; q++) {
            const unsigned int* u0 = reinterpret_cast<const unsigned int*>(&r0[q]);
            const unsigned int* u1 = reinterpret_cast<const unsigned int*>(&r1[q]);
            #pragma unroll
            for (int p = 0; p < 4; p++) {
                unsigned int b0v = u0[p], b1v = u1[p];
                float2 v0 = __half22float2(*reinterpret_cast<const __half2*>(&b0v));
                float2 v1 = __half22float2(*reinterpret_cast<const __half2*>(&b1v));
                int f = q * 8 + p * 2;
                {
                    unsigned long long hf0 = dup2(v0.x);
                    unsigned long long hf1 = dup2(v1.x);
                    const ulonglong2* wr =
                        reinterpret_cast<const ulonglong2*>(wk + f * FOUT);
                    #pragma unroll
                    for (int j = 0; j < 8; j++) {
                        ulonglong2 w = wr[j];
                        ffma2(a0[2 * j],     hf0, w.x);
                        ffma2(a0[2 * j + 1], hf0, w.y);
                        ffma2(a1[2 * j],     hf1, w.x);
                        ffma2(a1[2 * j + 1], hf1, w.y);
                    }
                }
                {
                    unsigned long long hf0 = dup2(v0.y);
                    unsigned long long hf1 = dup2(v1.y);
                    const ulonglong2* wr =
                        reinterpret_cast<const ulonglong2*>(wk + (f + 1) * FOUT);
                    #pragma unroll
                    for (int j = 0; j < 8; j++) {
                        ulonglong2 w = wr[j];
                        ffma2(a0[2 * j],     hf0, w.x);
                        ffma2(a0[2 * j + 1], hf0, w.y);
                        ffma2(a1[2 * j],     hf1, w.x);
                        ffma2(a1[2 * j + 1], hf1, w.y);
                    }
                }
            }
        }
    }

    finish_node(n0, a0, zf, zw, zb, out, off2);
    finish_node(n1, a1, zf, zw, zb, out, off2);
}

// ------------------------------- launcher -------------------------------------
extern "C" void kernel_launch(void* const* d_in, const int* in_sizes, int n_in,
                              void* d_out, int out_size) {
    const float* x    = (const float*)d_in[0];
    const float* zf   = (const float*)d_in[1];
    const int*   nbr  = (const int*)d_in[2];
    const float* w1   = (const float*)d_in[3];
    const float* g1   = (const float*)d_in[4];
    const float* b1   = (const float*)d_in[5];
    const float* m1   = (const float*)d_in[6];
    const float* v1   = (const float*)d_in[7];
    const float* w2   = (const float*)d_in[8];
    const float* mw   = (const float*)d_in[9];
    const float* mb   = (const float*)d_in[10];
    const float* mg   = (const float*)d_in[11];
    const float* mbt  = (const float*)d_in[12];
    const float* mm   = (const float*)d_in[13];
    const float* mv   = (const float*)d_in[14];
    float* out = (float*)d_out;

    // output is (fused, fused): second copy at out_size - N*FOUT (== 0 if the
    // harness deduplicates the tuple, in which case writes just coincide).
    size_t off2 = (size_t)out_size - (size_t)N_NODES * FOUT;

    pad_x_kernel<<<(N_NODES + 255) / 256, 256>>>(x);
    stage1_kernel<<<N_NODES / 256, 256>>>(nbr, w1, g1, b1, m1, v1);

    const int SMEM_B = (KNBR * FOUT * FOUT + FIN * FOUT + FOUT) * (int)sizeof(float);
    cudaFuncSetAttribute(stage2_kernel,
                         cudaFuncAttributeMaxDynamicSharedMemorySize, SMEM_B);
    stage2_kernel<<<N_NODES / 512, 256, SMEM_B>>>(
        nbr, w2, zf, mw, mb, mg, mbt, mm, mv, out, off2);
}

// round 7
// speedup vs baseline: 2.1303x; 2.1303x over previous
#include <cuda_runtime.h>
#include <cuda_fp16.h>

#define N_NODES 131072
#define KNBR    27
#define FIN     3
#define FOUT    32
#define EPS     1e-5f

// ---------------- scratch (static device arrays: no allocation) ----------------
// g_h: permuted fp16 h rows. Row = 8 groups x 8B; group g (tk=g>>2, c=g&3)
// holds halves {f0, f0+1, f0+8, f0+9} with f0 = 16*tk + 2*c.
__device__ __align__(16) unsigned long long g_h[(size_t)N_NODES * 8];   // 8 MB
__device__ __align__(16) float4 g_xp[N_NODES];                          // 2 MB
// w2 packed fp16, same group permutation, BN-free: [k][o][g] (o = out col)
__device__ __align__(16) unsigned long long g_w2p[KNBR * FOUT * 8];     // 55 KB

// ---------------- f32x2 packed-FMA helpers (stage 1) ---------------------------
__device__ __forceinline__ void ffma2(unsigned long long& d,
                                      unsigned long long a,
                                      unsigned long long b) {
    asm volatile("fma.rn.f32x2 %0, %1, %2, %0;" : "+l"(d) : "l"(a), "l"(b));
}
__device__ __forceinline__ unsigned long long dup2(float x) {
    unsigned long long r;
    asm("mov.b64 %0, {%1, %1};" : "=l"(r) : "f"(x));
    return r;
}
union U64F2 { unsigned long long u; float2 f; };

// ---------------- HMMA m16n8k16 row.col f16f16->f32 ----------------------------
__device__ __forceinline__ void hmma(float* d,
                                     unsigned long long aL,   // (a0 | a2<<32)
                                     unsigned long long aH,   // (a1 | a3<<32)
                                     unsigned long long b) {  // (b0 | b1<<32)
    unsigned a0 = (unsigned)aL, a2 = (unsigned)(aL >> 32);
    unsigned a1 = (unsigned)aH, a3 = (unsigned)(aH >> 32);
    unsigned b0 = (unsigned)b,  b1 = (unsigned)(b >> 32);
    asm volatile(
        "mma.sync.aligned.m16n8k16.row.col.f32.f16.f16.f32 "
        "{%0,%1,%2,%3}, {%4,%5,%6,%7}, {%8,%9}, {%0,%1,%2,%3};\n"
        : "+f"(d[0]), "+f"(d[1]), "+f"(d[2]), "+f"(d[3])
        : "r"(a0), "r"(a1), "r"(a2), "r"(a3), "r"(b0), "r"(b1));
}

// ---------------- kernel 0: pad x_feats rows to 16B ----------------------------
__global__ void pad_x_kernel(const float* __restrict__ x) {
    int n = blockIdx.x * blockDim.x + threadIdx.x;
    if (n < N_NODES) {
        float4 v;
        v.x = x[3 * (size_t)n];
        v.y = x[3 * (size_t)n + 1];
        v.z = x[3 * (size_t)n + 2];
        v.w = 0.f;
        g_xp[n] = v;
    }
}

// ---------------- kernel 0b: pack w2 -> fp16 permuted groups -------------------
__global__ void w2prep_kernel(const float* __restrict__ w2) {
    int t = blockIdx.x * 256 + threadIdx.x;
    if (t >= KNBR * FOUT * 8) return;
    int g = t & 7;
    int o = (t >> 3) & 31;
    int k = t >> 8;
    int f0 = ((g >> 2) << 4) + ((g & 3) << 1);
    const float* base = w2 + (size_t)k * FOUT * FOUT + o;  // stride FOUT over f
    __half2 lo = __floats2half2_rn(base[(size_t)f0 * FOUT],
                                   base[(size_t)(f0 + 1) * FOUT]);
    __half2 hi = __floats2half2_rn(base[(size_t)(f0 + 8) * FOUT],
                                   base[(size_t)(f0 + 9) * FOUT]);
    unsigned int ulo = *reinterpret_cast<unsigned int*>(&lo);
    unsigned int uhi = *reinterpret_cast<unsigned int*>(&hi);
    g_w2p[t] = ((unsigned long long)uhi << 32) | ulo;
}

// ---------------- kernel 1: h = silu(bn(gatherGEMM(x, w1))) -> permuted fp16 ---
__global__ __launch_bounds__(256) void stage1_kernel(
    const int*   __restrict__ nbr,
    const float* __restrict__ w1,
    const float* __restrict__ gamma1,
    const float* __restrict__ beta1,
    const float* __restrict__ mean1,
    const float* __restrict__ var1)
{
    __shared__ __align__(16) float wf[KNBR * FIN * FOUT];  // w1 * scale[o]
    __shared__ float ssc[FOUT];
    __shared__ float sb[FOUT];

    int tid = threadIdx.x;
    if (tid < FOUT) {
        float s = gamma1[tid] * rsqrtf(var1[tid] + EPS);
        ssc[tid] = s;
        sb[tid]  = beta1[tid] - mean1[tid] * s;
    }
    __syncthreads();
    for (int i = tid; i < KNBR * FIN * FOUT; i += 256)
        wf[i] = w1[i] * ssc[i & 31];
    __syncthreads();

    int n = blockIdx.x * 256 + tid;
    const int* nb = nbr + (size_t)n * KNBR;

    unsigned long long acc[16];
    #pragma unroll
    for (int j = 0; j < 16; j++) acc[j] = 0ull;

    #pragma unroll 1
    for (int k = 0; k < KNBR; k++) {
        int idx = nb[k];
        float4 xv = g_xp[idx];
        float xr[3] = {xv.x, xv.y, xv.z};
        #pragma unroll
        for (int f = 0; f < FIN; f++) {
            unsigned long long hf = dup2(xr[f]);
            const ulonglong2* wrow =
                reinterpret_cast<const ulonglong2*>(wf + (k * FIN + f) * FOUT);
            #pragma unroll
            for (int j = 0; j < 8; j++) {
                ulonglong2 w = wrow[j];
                ffma2(acc[2 * j],     hf, w.x);
                ffma2(acc[2 * j + 1], hf, w.y);
            }
        }
    }

    // bias + silu -> 16 half2 pair-words (pair j = channels {2j, 2j+1})
    unsigned int pw[16];
    #pragma unroll
    for (int j = 0; j < 16; j++) {
        U64F2 uv; uv.u = acc[j];
        float a0 = uv.f.x + sb[2 * j];
        float a1 = uv.f.y + sb[2 * j + 1];
        a0 = a0 / (1.f + __expf(-a0));     // silu
        a1 = a1 / (1.f + __expf(-a1));
        __half2 hh = __floats2half2_rn(a0, a1);
        pw[j] = *reinterpret_cast<unsigned int*>(&hh);
    }
    // permuted store: group g = (tk*4+c) -> words {pair[8*tk+c], pair[8*tk+c+4]}
    ulonglong2* dst = reinterpret_cast<ulonglong2*>(g_h + (size_t)n * 8);
    #pragma unroll
    for (int j = 0; j < 4; j++) {
        int g0 = 2 * j, g1 = 2 * j + 1;
        int p0 = 8 * (g0 >> 2) + (g0 & 3);
        int p1 = 8 * (g1 >> 2) + (g1 & 3);
        ulonglong2 v;
        v.x = ((unsigned long long)pw[p0 + 4] << 32) | pw[p0];
        v.y = ((unsigned long long)pw[p1 + 4] << 32) | pw[p1];
        dst[j] = v;
    }
}

// ---------------- kernel 2: tensorized gatherGEMM(h, w2) + mlp(z) + fuse -------
// warp = 32 nodes (2 m16 tiles); per neighbor: 16 HMMA (2 tiles x 4 n x 2 k)
__global__ __launch_bounds__(256, 2) void stage2_mma(
    const int*   __restrict__ nbr,
    const float* __restrict__ zf,
    const float* __restrict__ mw,
    const float* __restrict__ mb,
    const float* __restrict__ mg,
    const float* __restrict__ mbeta,
    const float* __restrict__ mmean,
    const float* __restrict__ mvar,
    float* __restrict__ out, size_t off2)
{
    extern __shared__ unsigned char smemRaw[];
    unsigned long long* w2s = reinterpret_cast<unsigned long long*>(smemRaw);
    float* zw = reinterpret_cast<float*>(smemRaw + KNBR * FOUT * 8 * 8);   // [3][32]
    float* zb = zw + FIN * FOUT;

    int tid = threadIdx.x;
    if (tid < FOUT) {
        float s = mg[tid] * rsqrtf(mvar[tid] + EPS);
        zb[tid] = (mb[tid] - mmean[tid]) * s + mbeta[tid];
        #pragma unroll
        for (int f = 0; f < FIN; f++)
            zw[f * FOUT + tid] = mw[f * FOUT + tid] * s;
    }
    {   // cooperative copy of packed w2 (55 KB) into smem
        const ulonglong2* src = reinterpret_cast<const ulonglong2*>(g_w2p);
        ulonglong2* dst = reinterpret_cast<ulonglong2*>(w2s);
        for (int i = tid; i < KNBR * FOUT * 4; i += 256) dst[i] = src[i];
    }
    __syncthreads();

    int warp = tid >> 5, lane = tid & 31;
    int gid = lane >> 2, c = lane & 3;
    int nbase = (blockIdx.x * 8 + warp) * 32;

    // neighbor-list row pointers: tile0 {lo,hi}, tile1 {lo,hi}
    const int* np0 = nbr + (size_t)(nbase + gid)      * KNBR;
    const int* np1 = nbr + (size_t)(nbase + 8 + gid)  * KNBR;
    const int* np2 = nbr + (size_t)(nbase + 16 + gid) * KNBR;
    const int* np3 = nbr + (size_t)(nbase + 24 + gid) * KNBR;

    float acc[2][4][4];
    #pragma unroll
    for (int t = 0; t < 2; t++)
        #pragma unroll
        for (int tn = 0; tn < 4; tn++)
            #pragma unroll
            for (int j = 0; j < 4; j++) acc[t][tn][j] = 0.f;

    const unsigned long long* hp = g_h;

    #pragma unroll 1
    for (int k = 0; k < KNBR; k++) {
        int i0 = np0[k], i1 = np1[k], i2 = np2[k], i3 = np3[k];

        unsigned long long aL0[2], aH0[2], aL1[2], aH1[2];
        #pragma unroll
        for (int tk = 0; tk < 2; tk++) {
            int go = tk * 4 + c;
            aL0[tk] = hp[(size_t)i0 * 8 + go];
            aH0[tk] = hp[(size_t)i1 * 8 + go];
            aL1[tk] = hp[(size_t)i2 * 8 + go];
            aH1[tk] = hp[(size_t)i3 * 8 + go];
        }

        const unsigned long long* wb = w2s + (size_t)k * 256 + c;
        #pragma unroll
        for (int tn = 0; tn < 4; tn++) {
            #pragma unroll
            for (int tk = 0; tk < 2; tk++) {
                unsigned long long bv = wb[(tn * 8 + gid) * 8 + tk * 4];
                hmma(acc[0][tn], aL0[tk], aH0[tk], bv);
                hmma(acc[1][tn], aL1[tk], aH1[tk], bv);
            }
        }
    }

    // ---- epilogue: add relu(bn(z @ mlp_w + b)), write both output copies -----
    #pragma unroll
    for (int t = 0; t < 2; t++) {
        int nlo = nbase + t * 16 + gid;
        int nhi = nlo + 8;
        float zl0 = zf[3 * (size_t)nlo],     zl1 = zf[3 * (size_t)nlo + 1],
              zl2 = zf[3 * (size_t)nlo + 2];
        float zh0 = zf[3 * (size_t)nhi],     zh1 = zf[3 * (size_t)nhi + 1],
              zh2 = zf[3 * (size_t)nhi + 2];
        #pragma unroll
        for (int tn = 0; tn < 4; tn++) {
            int col = tn * 8 + c * 2;
            float w00 = zw[col],      w01 = zw[32 + col],  w02 = zw[64 + col];
            float w10 = zw[col + 1],  w11 = zw[33 + col],  w12 = zw[65 + col];
            float b0v = zb[col], b1v = zb[col + 1];
            float zlo0 = fmaxf(fmaf(zl0, w00, fmaf(zl1, w01, fmaf(zl2, w02, b0v))), 0.f);
            float zlo1 = fmaxf(fmaf(zl0, w10, fmaf(zl1, w11, fmaf(zl2, w12, b1v))), 0.f);
            float zhi0 = fmaxf(fmaf(zh0, w00, fmaf(zh1, w01, fmaf(zh2, w02, b0v))), 0.f);
            float zhi1 = fmaxf(fmaf(zh0, w10, fmaf(zh1, w11, fmaf(zh2, w12, b1v))), 0.f);
            float2 vlo = make_float2(acc[t][tn][0] + zlo0, acc[t][tn][1] + zlo1);
            float2 vhi = make_float2(acc[t][tn][2] + zhi0, acc[t][tn][3] + zhi1);
            *reinterpret_cast<float2*>(out + (size_t)nlo * 32 + col) = vlo;
            *reinterpret_cast<float2*>(out + (size_t)nhi * 32 + col) = vhi;
            *reinterpret_cast<float2*>(out + off2 + (size_t)nlo * 32 + col) = vlo;
            *reinterpret_cast<float2*>(out + off2 + (size_t)nhi * 32 + col) = vhi;
        }
    }
}

// ------------------------------- launcher -------------------------------------
extern "C" void kernel_launch(void* const* d_in, const int* in_sizes, int n_in,
                              void* d_out, int out_size) {
    const float* x    = (const float*)d_in[0];
    const float* zf   = (const float*)d_in[1];
    const int*   nbr  = (const int*)d_in[2];
    const float* w1   = (const float*)d_in[3];
    const float* g1   = (const float*)d_in[4];
    const float* b1   = (const float*)d_in[5];
    const float* m1   = (const float*)d_in[6];
    const float* v1   = (const float*)d_in[7];
    const float* w2   = (const float*)d_in[8];
    const float* mw   = (const float*)d_in[9];
    const float* mb   = (const float*)d_in[10];
    const float* mg   = (const float*)d_in[11];
    const float* mbt  = (const float*)d_in[12];
    const float* mm   = (const float*)d_in[13];
    const float* mv   = (const float*)d_in[14];
    float* out = (float*)d_out;

    size_t off2 = (size_t)out_size - (size_t)N_NODES * FOUT;

    pad_x_kernel<<<(N_NODES + 255) / 256, 256>>>(x);
    w2prep_kernel<<<(KNBR * FOUT * 8 + 255) / 256, 256>>>(w2);
    stage1_kernel<<<N_NODES / 256, 256>>>(nbr, w1, g1, b1, m1, v1);

    const int SMEM_B = KNBR * FOUT * 8 * 8 + (FIN * FOUT + FOUT) * (int)sizeof(float);
    cudaFuncSetAttribute(stage2_mma,
                         cudaFuncAttributeMaxDynamicSharedMemorySize, SMEM_B);
    stage2_mma<<<N_NODES / 256, 256, SMEM_B>>>(
        nbr, zf, mw, mb, mg, mbt, mm, mv, out, off2);
}

// round 8
// speedup vs baseline: 2.2979x; 1.0787x over previous
#include <cuda_runtime.h>
#include <cuda_fp16.h>

#define N_NODES 131072
#define KNBR    27
#define FIN     3
#define FOUT    32
#define EPS     1e-5f

// ---------------- scratch (static device arrays: no allocation) ----------------
// g_h permuted fp16 rows, 64B/row = 8 groups x 8B, position p = c*2 + tk
// (c = lane&3 quad-pair, tk = k16-chunk). Group (tk,c) holds halves
// {16tk+2c, 16tk+2c+1, 16tk+2c+8, 16tk+2c+9}  (= a0|a2 of the MMA A-fragment).
// => one LDG.128 at row*64 + c*16 gives lane (gid,c) BOTH tk fragments.
__device__ __align__(16) unsigned long long g_h[(size_t)N_NODES * 8];   // 8 MB
__device__ __align__(16) float4 g_xp[N_NODES];                          // 2 MB
// w2 packed fp16: [k][o][g], g = tk*4+c, content halves {16tk+2c,+1,+8,+9}
__device__ __align__(16) unsigned long long g_w2p[KNBR * FOUT * 8];     // 55 KB

// ---------------- f32x2 packed-FMA helpers (stage 1) ---------------------------
__device__ __forceinline__ void ffma2(unsigned long long& d,
                                      unsigned long long a,
                                      unsigned long long b) {
    asm volatile("fma.rn.f32x2 %0, %1, %2, %0;" : "+l"(d) : "l"(a), "l"(b));
}
__device__ __forceinline__ unsigned long long dup2(float x) {
    unsigned long long r;
    asm("mov.b64 %0, {%1, %1};" : "=l"(r) : "f"(x));
    return r;
}
union U64F2 { unsigned long long u; float2 f; };

// ---------------- HMMA m16n8k16 row.col f16f16->f32 ----------------------------
__device__ __forceinline__ void hmma(float* d,
                                     unsigned long long aL,   // (a0 | a2<<32)
                                     unsigned long long aH,   // (a1 | a3<<32)
                                     unsigned long long b) {  // (b0 | b1<<32)
    unsigned a0 = (unsigned)aL, a2 = (unsigned)(aL >> 32);
    unsigned a1 = (unsigned)aH, a3 = (unsigned)(aH >> 32);
    unsigned b0 = (unsigned)b,  b1 = (unsigned)(b >> 32);
    asm volatile(
        "mma.sync.aligned.m16n8k16.row.col.f32.f16.f16.f32 "
        "{%0,%1,%2,%3}, {%4,%5,%6,%7}, {%8,%9}, {%0,%1,%2,%3};\n"
        : "+f"(d[0]), "+f"(d[1]), "+f"(d[2]), "+f"(d[3])
        : "r"(a0), "r"(a1), "r"(a2), "r"(a3), "r"(b0), "r"(b1));
}

__device__ __forceinline__ unsigned long long pk64(unsigned lo, unsigned hi) {
    return ((unsigned long long)hi << 32) | lo;
}

// ---------------- kernel 0: pad x_feats rows to 16B ----------------------------
__global__ void pad_x_kernel(const float* __restrict__ x) {
    int n = blockIdx.x * blockDim.x + threadIdx.x;
    if (n < N_NODES) {
        float4 v;
        v.x = x[3 * (size_t)n];
        v.y = x[3 * (size_t)n + 1];
        v.z = x[3 * (size_t)n + 2];
        v.w = 0.f;
        g_xp[n] = v;
    }
}

// ---------------- kernel 0b: pack w2 -> fp16 permuted groups -------------------
__global__ void w2prep_kernel(const float* __restrict__ w2) {
    int t = blockIdx.x * 256 + threadIdx.x;
    if (t >= KNBR * FOUT * 8) return;
    int g = t & 7;
    int o = (t >> 3) & 31;
    int k = t >> 8;
    int f0 = ((g >> 2) << 4) + ((g & 3) << 1);
    const float* base = w2 + (size_t)k * FOUT * FOUT + o;  // stride FOUT over f
    __half2 lo = __floats2half2_rn(base[(size_t)f0 * FOUT],
                                   base[(size_t)(f0 + 1) * FOUT]);
    __half2 hi = __floats2half2_rn(base[(size_t)(f0 + 8) * FOUT],
                                   base[(size_t)(f0 + 9) * FOUT]);
    unsigned int ulo = *reinterpret_cast<unsigned int*>(&lo);
    unsigned int uhi = *reinterpret_cast<unsigned int*>(&hi);
    g_w2p[t] = ((unsigned long long)uhi << 32) | ulo;
}

// ---------------- kernel 1: h = silu(bn(gatherGEMM(x, w1))) -> permuted fp16 ---
__global__ __launch_bounds__(256) void stage1_kernel(
    const int*   __restrict__ nbr,
    const float* __restrict__ w1,
    const float* __restrict__ gamma1,
    const float* __restrict__ beta1,
    const float* __restrict__ mean1,
    const float* __restrict__ var1)
{
    __shared__ __align__(16) float wf[KNBR * FIN * FOUT];  // w1 * scale[o]
    __shared__ float ssc[FOUT];
    __shared__ float sb[FOUT];

    int tid = threadIdx.x;
    if (tid < FOUT) {
        float s = gamma1[tid] * rsqrtf(var1[tid] + EPS);
        ssc[tid] = s;
        sb[tid]  = beta1[tid] - mean1[tid] * s;
    }
    __syncthreads();
    for (int i = tid; i < KNBR * FIN * FOUT; i += 256)
        wf[i] = w1[i] * ssc[i & 31];
    __syncthreads();

    int n = blockIdx.x * 256 + tid;
    const int* nb = nbr + (size_t)n * KNBR;

    unsigned long long acc[16];
    #pragma unroll
    for (int j = 0; j < 16; j++) acc[j] = 0ull;

    #pragma unroll 3
    for (int k = 0; k < KNBR; k++) {
        int idx = nb[k];
        float4 xv = g_xp[idx];
        float xr[3] = {xv.x, xv.y, xv.z};
        #pragma unroll
        for (int f = 0; f < FIN; f++) {
            unsigned long long hf = dup2(xr[f]);
            const ulonglong2* wrow =
                reinterpret_cast<const ulonglong2*>(wf + (k * FIN + f) * FOUT);
            #pragma unroll
            for (int j = 0; j < 8; j++) {
                ulonglong2 w = wrow[j];
                ffma2(acc[2 * j],     hf, w.x);
                ffma2(acc[2 * j + 1], hf, w.y);
            }
        }
    }

    // bias + silu -> 16 half2 pair-words (pair j = channels {2j, 2j+1})
    unsigned int pw[16];
    #pragma unroll
    for (int j = 0; j < 16; j++) {
        U64F2 uv; uv.u = acc[j];
        float a0 = uv.f.x + sb[2 * j];
        float a1 = uv.f.y + sb[2 * j + 1];
        a0 = a0 / (1.f + __expf(-a0));     // silu
        a1 = a1 / (1.f + __expf(-a1));
        __half2 hh = __floats2half2_rn(a0, a1);
        pw[j] = *reinterpret_cast<unsigned int*>(&hh);
    }
    // c-major permuted store: position p = c*2 + tk
    //   word(p) = pair[8*tk + c] | pair[8*tk + c + 4] << 32
    ulonglong2* dst = reinterpret_cast<ulonglong2*>(g_h + (size_t)n * 8);
    #pragma unroll
    for (int j = 0; j < 4; j++) {      // j = c
        ulonglong2 v;
        v.x = pk64(pw[j],     pw[j + 4]);   // tk = 0
        v.y = pk64(pw[8 + j], pw[12 + j]);  // tk = 1
        dst[j] = v;
    }
}

// ---------------- stage-2 inner compute: 16 HMMA from 4 gathered uint4 ---------
__device__ __forceinline__ void mma_step(
    float acc[2][4][4],
    uint4 r0, uint4 r1, uint4 r2, uint4 r3,
    const unsigned long long* __restrict__ wb, int gid)
{
    // r: lane(gid,c) holds row's bytes [c*16, c*16+16) = {tk0 group, tk1 group}
    unsigned long long aL0[2] = { pk64(r0.x, r0.y), pk64(r0.z, r0.w) };
    unsigned long long aH0[2] = { pk64(r1.x, r1.y), pk64(r1.z, r1.w) };
    unsigned long long aL1[2] = { pk64(r2.x, r2.y), pk64(r2.z, r2.w) };
    unsigned long long aH1[2] = { pk64(r3.x, r3.y), pk64(r3.z, r3.w) };

    #pragma unroll
    for (int tn = 0; tn < 4; tn++) {
        #pragma unroll
        for (int tk = 0; tk < 2; tk++) {
            unsigned long long bv = wb[(tn * 8 + gid) * 8 + tk * 4];
            hmma(acc[0][tn], aL0[tk], aH0[tk], bv);
            hmma(acc[1][tn], aL1[tk], aH1[tk], bv);
        }
    }
}

// ---------------- kernel 2: tensorized gatherGEMM(h, w2) + mlp(z) + fuse -------
__global__ __launch_bounds__(256, 2) void stage2_mma(
    const int*   __restrict__ nbr,
    const float* __restrict__ zf,
    const float* __restrict__ mw,
    const float* __restrict__ mb,
    const float* __restrict__ mg,
    const float* __restrict__ mbeta,
    const float* __restrict__ mmean,
    const float* __restrict__ mvar,
    float* __restrict__ out, size_t off2)
{
    extern __shared__ unsigned char smemRaw[];
    unsigned long long* w2s = reinterpret_cast<unsigned long long*>(smemRaw);
    float* zw = reinterpret_cast<float*>(smemRaw + KNBR * FOUT * 8 * 8);   // [3][32]
    float* zb = zw + FIN * FOUT;

    int tid = threadIdx.x;
    if (tid < FOUT) {
        float s = mg[tid] * rsqrtf(mvar[tid] + EPS);
        zb[tid] = (mb[tid] - mmean[tid]) * s + mbeta[tid];
        #pragma unroll
        for (int f = 0; f < FIN; f++)
            zw[f * FOUT + tid] = mw[f * FOUT + tid] * s;
    }
    {   // cooperative copy of packed w2 (55 KB) into smem
        const ulonglong2* src = reinterpret_cast<const ulonglong2*>(g_w2p);
        ulonglong2* dst = reinterpret_cast<ulonglong2*>(w2s);
        for (int i = tid; i < KNBR * FOUT * 4; i += 256) dst[i] = src[i];
    }
    __syncthreads();

    int warp = tid >> 5, lane = tid & 31;
    int gid = lane >> 2, c = lane & 3;
    int nbase = (blockIdx.x * 8 + warp) * 32;

    const int* np0 = nbr + (size_t)(nbase + gid)      * KNBR;
    const int* np1 = nbr + (size_t)(nbase + 8 + gid)  * KNBR;
    const int* np2 = nbr + (size_t)(nbase + 16 + gid) * KNBR;
    const int* np3 = nbr + (size_t)(nbase + 24 + gid) * KNBR;

    float acc[2][4][4];
    #pragma unroll
    for (int t = 0; t < 2; t++)
        #pragma unroll
        for (int tn = 0; tn < 4; tn++)
            #pragma unroll
            for (int j = 0; j < 4; j++) acc[t][tn][j] = 0.f;

    const uint4* hb = reinterpret_cast<const uint4*>(g_h);   // 4 uint4 / row
    unsigned cu = (unsigned)c;

    // prologue: gather k = 0
    uint4 r0 = hb[(unsigned)np0[0] * 4u + cu];
    uint4 r1 = hb[(unsigned)np1[0] * 4u + cu];
    uint4 r2 = hb[(unsigned)np2[0] * 4u + cu];
    uint4 r3 = hb[(unsigned)np3[0] * 4u + cu];

    const unsigned long long* wb = w2s + c;

    #pragma unroll 1
    for (int k = 0; k < KNBR - 1; k++) {
        // prefetch k+1 (idx + A rows) before consuming k
        uint4 n0 = hb[(unsigned)np0[k + 1] * 4u + cu];
        uint4 n1 = hb[(unsigned)np1[k + 1] * 4u + cu];
        uint4 n2 = hb[(unsigned)np2[k + 1] * 4u + cu];
        uint4 n3 = hb[(unsigned)np3[k + 1] * 4u + cu];

        mma_step(acc, r0, r1, r2, r3, wb, gid);
        wb += 256;
        r0 = n0; r1 = n1; r2 = n2; r3 = n3;
    }
    mma_step(acc, r0, r1, r2, r3, wb, gid);   // k = 26

    // ---- epilogue: add relu(bn(z @ mlp_w + b)), write both output copies -----
    #pragma unroll
    for (int t = 0; t < 2; t++) {
        int nlo = nbase + t * 16 + gid;
        int nhi = nlo + 8;
        float zl0 = zf[3 * (size_t)nlo],     zl1 = zf[3 * (size_t)nlo + 1],
              zl2 = zf[3 * (size_t)nlo + 2];
        float zh0 = zf[3 * (size_t)nhi],     zh1 = zf[3 * (size_t)nhi + 1],
              zh2 = zf[3 * (size_t)nhi + 2];
        #pragma unroll
        for (int tn = 0; tn < 4; tn++) {
            int col = tn * 8 + c * 2;
            float w00 = zw[col],      w01 = zw[32 + col],  w02 = zw[64 + col];
            float w10 = zw[col + 1],  w11 = zw[33 + col],  w12 = zw[65 + col];
            float b0v = zb[col], b1v = zb[col + 1];
            float zlo0 = fmaxf(fmaf(zl0, w00, fmaf(zl1, w01, fmaf(zl2, w02, b0v))), 0.f);
            float zlo1 = fmaxf(fmaf(zl0, w10, fmaf(zl1, w11, fmaf(zl2, w12, b1v))), 0.f);
            float zhi0 = fmaxf(fmaf(zh0, w00, fmaf(zh1, w01, fmaf(zh2, w02, b0v))), 0.f);
            float zhi1 = fmaxf(fmaf(zh0, w10, fmaf(zh1, w11, fmaf(zh2, w12, b1v))), 0.f);
            float2 vlo = make_float2(acc[t][tn][0] + zlo0, acc[t][tn][1] + zlo1);
            float2 vhi = make_float2(acc[t][tn][2] + zhi0, acc[t][tn][3] + zhi1);
            *reinterpret_cast<float2*>(out + (size_t)nlo * 32 + col) = vlo;
            *reinterpret_cast<float2*>(out + (size_t)nhi * 32 + col) = vhi;
            *reinterpret_cast<float2*>(out + off2 + (size_t)nlo * 32 + col) = vlo;
            *reinterpret_cast<float2*>(out + off2 + (size_t)nhi * 32 + col) = vhi;
        }
    }
}

// ------------------------------- launcher -------------------------------------
extern "C" void kernel_launch(void* const* d_in, const int* in_sizes, int n_in,
                              void* d_out, int out_size) {
    const float* x    = (const float*)d_in[0];
    const float* zf   = (const float*)d_in[1];
    const int*   nbr  = (const int*)d_in[2];
    const float* w1   = (const float*)d_in[3];
    const float* g1   = (const float*)d_in[4];
    const float* b1   = (const float*)d_in[5];
    const float* m1   = (const float*)d_in[6];
    const float* v1   = (const float*)d_in[7];
    const float* w2   = (const float*)d_in[8];
    const float* mw   = (const float*)d_in[9];
    const float* mb   = (const float*)d_in[10];
    const float* mg   = (const float*)d_in[11];
    const float* mbt  = (const float*)d_in[12];
    const float* mm   = (const float*)d_in[13];
    const float* mv   = (const float*)d_in[14];
    float* out = (float*)d_out;

    size_t off2 = (size_t)out_size - (size_t)N_NODES * FOUT;

    pad_x_kernel<<<(N_NODES + 255) / 256, 256>>>(x);
    w2prep_kernel<<<(KNBR * FOUT * 8 + 255) / 256, 256>>>(w2);
    stage1_kernel<<<N_NODES / 256, 256>>>(nbr, w1, g1, b1, m1, v1);

    const int SMEM_B = KNBR * FOUT * 8 * 8 + (FIN * FOUT + FOUT) * (int)sizeof(float);
    cudaFuncSetAttribute(stage2_mma,
                         cudaFuncAttributeMaxDynamicSharedMemorySize, SMEM_B);
    stage2_mma<<<N_NODES / 256, 256, SMEM_B>>>(
        nbr, zf, mw, mb, mg, mbt, mm, mv, out, off2);
}

// round 11
// speedup vs baseline: 2.8117x; 1.2236x over previous
#include <cuda_runtime.h>
#include <cuda_fp16.h>

#define N_NODES 131072
#define KNBR    27
#define FIN     3
#define FOUT    32
#define EPS     1e-5f

// ---------------- scratch (static device arrays: no allocation) ----------------
// g_h permuted fp16 rows, 64B/row = 8 groups x 8B, position p = c*2 + tk.
// Group (tk,c) holds halves {16tk+2c, 16tk+2c+1, 16tk+2c+8, 16tk+2c+9}.
__device__ __align__(16) unsigned long long g_h[(size_t)N_NODES * 8];   // 8 MB
__device__ __align__(16) float4 g_xp[N_NODES];                          // 2 MB
// w2 packed fp16: [k][o][g], g = tk*4+c
__device__ __align__(16) unsigned long long g_w2p[KNBR * FOUT * 8];     // 55 KB

// ---------------- helpers -------------------------------------------------------
__device__ __forceinline__ void ffma2(unsigned long long& d,
                                      unsigned long long a,
                                      unsigned long long b) {
    asm volatile("fma.rn.f32x2 %0, %1, %2, %0;" : "+l"(d) : "l"(a), "l"(b));
}
__device__ __forceinline__ unsigned long long dup2(float x) {
    unsigned long long r;
    asm("mov.b64 %0, {%1, %1};" : "=l"(r) : "f"(x));
    return r;
}
union U64F2 { unsigned long long u; float2 f; };

__device__ __forceinline__ void hmma(float* d,
                                     unsigned long long aL,
                                     unsigned long long aH,
                                     unsigned long long b) {
    unsigned a0 = (unsigned)aL, a2 = (unsigned)(aL >> 32);
    unsigned a1 = (unsigned)aH, a3 = (unsigned)(aH >> 32);
    unsigned b0 = (unsigned)b,  b1 = (unsigned)(b >> 32);
    asm volatile(
        "mma.sync.aligned.m16n8k16.row.col.f32.f16.f16.f32 "
        "{%0,%1,%2,%3}, {%4,%5,%6,%7}, {%8,%9}, {%0,%1,%2,%3};\n"
        : "+f"(d[0]), "+f"(d[1]), "+f"(d[2]), "+f"(d[3])
        : "r"(a0), "r"(a1), "r"(a2), "r"(a3), "r"(b0), "r"(b1));
}
__device__ __forceinline__ unsigned long long pk64(unsigned lo, unsigned hi) {
    return ((unsigned long long)hi << 32) | lo;
}
__device__ __forceinline__ void cp_async16(unsigned saddr, const void* gaddr) {
    asm volatile("cp.async.cg.shared.global [%0], [%1], 16;\n"
                 :: "r"(saddr), "l"(gaddr));
}
__device__ __forceinline__ void cp_commit() {
    asm volatile("cp.async.commit_group;\n");
}
template <int N>
__device__ __forceinline__ void cp_wait() {
    asm volatile("cp.async.wait_group %0;\n" :: "n"(N));
}
__device__ __forceinline__ uint4 lds128(unsigned addr) {
    uint4 v;
    asm volatile("ld.shared.v4.u32 {%0,%1,%2,%3}, [%4];"
                 : "=r"(v.x), "=r"(v.y), "=r"(v.z), "=r"(v.w) : "r"(addr));
    return v;
}

// ---------------- kernel 0: pad x rows + pack w2, one launch -------------------
__global__ void prep_kernel(const float* __restrict__ x,
                            const float* __restrict__ w2) {
    int bid = blockIdx.x;
    int tid = threadIdx.x;
    if (bid < N_NODES / 256) {
        int n = bid * 256 + tid;
        float4 v;
        v.x = x[3 * (size_t)n];
        v.y = x[3 * (size_t)n + 1];
        v.z = x[3 * (size_t)n + 2];
        v.w = 0.f;
        g_xp[n] = v;
    } else {
        int t = (bid - N_NODES / 256) * 256 + tid;
        if (t >= KNBR * FOUT * 8) return;
        int g = t & 7;
        int o = (t >> 3) & 31;
        int k = t >> 8;
        int f0 = ((g >> 2) << 4) + ((g & 3) << 1);
        const float* base = w2 + (size_t)k * FOUT * FOUT + o;
        __half2 lo = __floats2half2_rn(base[(size_t)f0 * FOUT],
                                       base[(size_t)(f0 + 1) * FOUT]);
        __half2 hi = __floats2half2_rn(base[(size_t)(f0 + 8) * FOUT],
                                       base[(size_t)(f0 + 9) * FOUT]);
        unsigned ulo = *reinterpret_cast<unsigned*>(&lo);
        unsigned uhi = *reinterpret_cast<unsigned*>(&hi);
        g_w2p[t] = pk64(ulo, uhi);
    }
}

// ---------------- kernel 1: h = silu(bn(gatherGEMM(x, w1))) -> permuted fp16 ---
// 2 nodes/thread: weight LDS shared across both nodes, 4 gathers in flight.
__device__ __forceinline__ void s1_store(int n, const unsigned long long* acc,
                                         const float* sb) {
    unsigned pw[16];
    #pragma unroll
    for (int j = 0; j < 16; j++) {
        U64F2 uv; uv.u = acc[j];
        float a0 = uv.f.x + sb[2 * j];
        float a1 = uv.f.y + sb[2 * j + 1];
        a0 = a0 / (1.f + __expf(-a0));
        a1 = a1 / (1.f + __expf(-a1));
        __half2 hh = __floats2half2_rn(a0, a1);
        pw[j] = *reinterpret_cast<unsigned*>(&hh);
    }
    ulonglong2* dst = reinterpret_cast<ulonglong2*>(g_h + (size_t)n * 8);
    #pragma unroll
    for (int j = 0; j < 4; j++) {
        ulonglong2 v;
        v.x = pk64(pw[j],     pw[j + 4]);
        v.y = pk64(pw[8 + j], pw[12 + j]);
        dst[j] = v;
    }
}

__global__ __launch_bounds__(256) void stage1_kernel(
    const int*   __restrict__ nbr,
    const float* __restrict__ w1,
    const float* __restrict__ gamma1,
    const float* __restrict__ beta1,
    const float* __restrict__ mean1,
    const float* __restrict__ var1)
{
    __shared__ __align__(16) float wf[KNBR * FIN * FOUT];
    __shared__ float ssc[FOUT];
    __shared__ float sb[FOUT];

    int tid = threadIdx.x;
    if (tid < FOUT) {
        float s = gamma1[tid] * rsqrtf(var1[tid] + EPS);
        ssc[tid] = s;
        sb[tid]  = beta1[tid] - mean1[tid] * s;
    }
    __syncthreads();
    for (int i = tid; i < KNBR * FIN * FOUT; i += 256)
        wf[i] = w1[i] * ssc[i & 31];
    __syncthreads();

    int n0 = blockIdx.x * 512 + tid;
    int n1 = n0 + 256;
    const int* nb0 = nbr + (size_t)n0 * KNBR;
    const int* nb1 = nbr + (size_t)n1 * KNBR;

    unsigned long long acc0[16], acc1[16];
    #pragma unroll
    for (int j = 0; j < 16; j++) { acc0[j] = 0ull; acc1[j] = 0ull; }

    #pragma unroll 3
    for (int k = 0; k < KNBR; k++) {
        int i0 = nb0[k];
        int i1 = nb1[k];
        float4 xa = g_xp[i0];
        float4 xb = g_xp[i1];
        float ra[3] = {xa.x, xa.y, xa.z};
        float rb[3] = {xb.x, xb.y, xb.z};
        #pragma unroll
        for (int f = 0; f < FIN; f++) {
            unsigned long long h0 = dup2(ra[f]);
            unsigned long long h1 = dup2(rb[f]);
            const ulonglong2* wrow =
                reinterpret_cast<const ulonglong2*>(wf + (k * FIN + f) * FOUT);
            #pragma unroll
            for (int j = 0; j < 8; j++) {
                ulonglong2 w = wrow[j];
                ffma2(acc0[2 * j],     h0, w.x);
                ffma2(acc0[2 * j + 1], h0, w.y);
                ffma2(acc1[2 * j],     h1, w.x);
                ffma2(acc1[2 * j + 1], h1, w.y);
            }
        }
    }
    s1_store(n0, acc0, sb);
    s1_store(n1, acc1, sb);
}

// ---------------- stage-2 inner compute ----------------------------------------
__device__ __forceinline__ void mma_step(
    float acc[2][4][4],
    uint4 r0, uint4 r1, uint4 r2, uint4 r3,
    const unsigned long long* __restrict__ wb, int gid)
{
    unsigned long long aL0[2] = { pk64(r0.x, r0.y), pk64(r0.z, r0.w) };
    unsigned long long aH0[2] = { pk64(r1.x, r1.y), pk64(r1.z, r1.w) };
    unsigned long long aL1[2] = { pk64(r2.x, r2.y), pk64(r2.z, r2.w) };
    unsigned long long aH1[2] = { pk64(r3.x, r3.y), pk64(r3.z, r3.w) };

    #pragma unroll
    for (int tn = 0; tn < 4; tn++) {
        #pragma unroll
        for (int tk = 0; tk < 2; tk++) {
            unsigned long long bv = wb[(tn * 8 + gid) * 8 + tk * 4];
            hmma(acc[0][tn], aL0[tk], aH0[tk], bv);
            hmma(acc[1][tn], aL1[tk], aH1[tk], bv);
        }
    }
}

// ---------------- kernel 2: cp.async 3-stage pipelined gather-MMA --------------
#define W2S_BYTES  (KNBR * FOUT * 8 * 8)          // 55296
#define ZWB_BYTES  ((FIN * FOUT + FOUT) * 4)      // 512
#define A_OFF      (W2S_BYTES + ZWB_BYTES)        // 55808 (16B aligned)
#define A_WARP     (3 * 2048)                     // 3 stages x 2KB
#define SMEM_TOT   (A_OFF + 8 * A_WARP)           // 104960

__global__ __launch_bounds__(256, 2) void stage2_mma(
    const int*   __restrict__ nbr,
    const float* __restrict__ zf,
    const float* __restrict__ mw,
    const float* __restrict__ mb,
    const float* __restrict__ mg,
    const float* __restrict__ mbeta,
    const float* __restrict__ mmean,
    const float* __restrict__ mvar,
    float* __restrict__ out, size_t off2)
{
    extern __shared__ unsigned char smemRaw[];
    unsigned long long* w2s = reinterpret_cast<unsigned long long*>(smemRaw);
    float* zw = reinterpret_cast<float*>(smemRaw + W2S_BYTES);
    float* zb = zw + FIN * FOUT;

    int tid = threadIdx.x;
    if (tid < FOUT) {
        float s = mg[tid] * rsqrtf(mvar[tid] + EPS);
        zb[tid] = (mb[tid] - mmean[tid]) * s + mbeta[tid];
        #pragma unroll
        for (int f = 0; f < FIN; f++)
            zw[f * FOUT + tid] = mw[f * FOUT + tid] * s;
    }
    {
        const ulonglong2* src = reinterpret_cast<const ulonglong2*>(g_w2p);
        ulonglong2* dst = reinterpret_cast<ulonglong2*>(w2s);
        for (int i = tid; i < KNBR * FOUT * 4; i += 256) dst[i] = src[i];
    }
    __syncthreads();

    int warp = tid >> 5, lane = tid & 31;
    int gid = lane >> 2, c = lane & 3;
    int nbase = (blockIdx.x * 8 + warp) * 32;

    const int* np0 = nbr + (size_t)(nbase + gid)      * KNBR;
    const int* np1 = nbr + (size_t)(nbase + 8 + gid)  * KNBR;
    const int* np2 = nbr + (size_t)(nbase + 16 + gid) * KNBR;
    const int* np3 = nbr + (size_t)(nbase + 24 + gid) * KNBR;

    float acc[2][4][4];
    #pragma unroll
    for (int t = 0; t < 2; t++)
        #pragma unroll
        for (int tn = 0; tn < 4; tn++)
            #pragma unroll
            for (int j = 0; j < 4; j++) acc[t][tn][j] = 0.f;

    // per-lane smem slot base: stage s, row-tile t -> aBase + s*2048 + t*512
    unsigned aBase = (unsigned)__cvta_generic_to_shared(smemRaw + A_OFF)
                   + warp * A_WARP + gid * 64 + c * 16;
    const char* hB = reinterpret_cast<const char*>(g_h);
    unsigned cOff = (unsigned)c * 16u;

    // prologue: stages for k = 0,1,2
    #pragma unroll
    for (int s = 0; s < 3; s++) {
        cp_async16(aBase + s * 2048 + 0,    hB + (size_t)(unsigned)np0[s] * 64 + cOff);
        cp_async16(aBase + s * 2048 + 512,  hB + (size_t)(unsigned)np1[s] * 64 + cOff);
        cp_async16(aBase + s * 2048 + 1024, hB + (size_t)(unsigned)np2[s] * 64 + cOff);
        cp_async16(aBase + s * 2048 + 1536, hB + (size_t)(unsigned)np3[s] * 64 + cOff);
        cp_commit();
    }
    // idx for k+3 (consumed at iter k), preloaded one iteration ahead
    int ia0 = np0[3], ia1 = np1[3], ia2 = np2[3], ia3 = np3[3];

    const unsigned long long* wb = w2s + c;
    unsigned sOff = 0;

    #pragma unroll 1
    for (int k = 0; k < KNBR - 3; k++) {
        cp_wait<2>();                           // stage k ready
        uint4 r0 = lds128(aBase + sOff + 0);
        uint4 r1 = lds128(aBase + sOff + 512);
        uint4 r2 = lds128(aBase + sOff + 1024);
        uint4 r3 = lds128(aBase + sOff + 1536);
        mma_step(acc, r0, r1, r2, r3, wb, gid);
        wb += 256;

        // refill same stage with k+3
        cp_async16(aBase + sOff + 0,    hB + (size_t)(unsigned)ia0 * 64 + cOff);
        cp_async16(aBase + sOff + 512,  hB + (size_t)(unsigned)ia1 * 64 + cOff);
        cp_async16(aBase + sOff + 1024, hB + (size_t)(unsigned)ia2 * 64 + cOff);
        cp_async16(aBase + sOff + 1536, hB + (size_t)(unsigned)ia3 * 64 + cOff);
        cp_commit();

        int kn = (k + 4 < KNBR) ? k + 4 : KNBR - 1;
        ia0 = np0[kn]; ia1 = np1[kn]; ia2 = np2[kn]; ia3 = np3[kn];

        sOff = (sOff == 4096u) ? 0u : sOff + 2048u;
    }
    // tail: k = 24, 25, 26
    {
        cp_wait<2>();
        uint4 r0 = lds128(aBase + sOff), r1 = lds128(aBase + sOff + 512);
        uint4 r2 = lds128(aBase + sOff + 1024), r3 = lds128(aBase + sOff + 1536);
        mma_step(acc, r0, r1, r2, r3, wb, gid); wb += 256;
        sOff = (sOff == 4096u) ? 0u : sOff + 2048u;
    }
    {
        cp_wait<1>();
        uint4 r0 = lds128(aBase + sOff), r1 = lds128(aBase + sOff + 512);
        uint4 r2 = lds128(aBase + sOff + 1024), r3 = lds128(aBase + sOff + 1536);
        mma_step(acc, r0, r1, r2, r3, wb, gid); wb += 256;
        sOff = (sOff == 4096u) ? 0u : sOff + 2048u;
    }
    {
        cp_wait<0>();
        uint4 r0 = lds128(aBase + sOff), r1 = lds128(aBase + sOff + 512);
        uint4 r2 = lds128(aBase + sOff + 1024), r3 = lds128(aBase + sOff + 1536);
        mma_step(acc, r0, r1, r2, r3, wb, gid);
    }

    // ---- epilogue: add relu(bn(z @ mlp_w + b)), write both output copies -----
    #pragma unroll
    for (int t = 0; t < 2; t++) {
        int nlo = nbase + t * 16 + gid;
        int nhi = nlo + 8;
        float zl0 = zf[3 * (size_t)nlo],     zl1 = zf[3 * (size_t)nlo + 1],
              zl2 = zf[3 * (size_t)nlo + 2];
        float zh0 = zf[3 * (size_t)nhi],     zh1 = zf[3 * (size_t)nhi + 1],
              zh2 = zf[3 * (size_t)nhi + 2];
        #pragma unroll
        for (int tn = 0; tn < 4; tn++) {
            int col = tn * 8 + c * 2;
            float w00 = zw[col],      w01 = zw[32 + col],  w02 = zw[64 + col];
            float w10 = zw[col + 1],  w11 = zw[33 + col],  w12 = zw[65 + col];
            float b0v = zb[col], b1v = zb[col + 1];
            float zlo0 = fmaxf(fmaf(zl0, w00, fmaf(zl1, w01, fmaf(zl2, w02, b0v))), 0.f);
            float zlo1 = fmaxf(fmaf(zl0, w10, fmaf(zl1, w11, fmaf(zl2, w12, b1v))), 0.f);
            float zhi0 = fmaxf(fmaf(zh0, w00, fmaf(zh1, w01, fmaf(zh2, w02, b0v))), 0.f);
            float zhi1 = fmaxf(fmaf(zh0, w10, fmaf(zh1, w11, fmaf(zh2, w12, b1v))), 0.f);
            float2 vlo = make_float2(acc[t][tn][0] + zlo0, acc[t][tn][1] + zlo1);
            float2 vhi = make_float2(acc[t][tn][2] + zhi0, acc[t][tn][3] + zhi1);
            *reinterpret_cast<float2*>(out + (size_t)nlo * 32 + col) = vlo;
            *reinterpret_cast<float2*>(out + (size_t)nhi * 32 + col) = vhi;
            *reinterpret_cast<float2*>(out + off2 + (size_t)nlo * 32 + col) = vlo;
            *reinterpret_cast<float2*>(out + off2 + (size_t)nhi * 32 + col) = vhi;
        }
    }
}

// ------------------------------- launcher -------------------------------------
extern "C" void kernel_launch(void* const* d_in, const int* in_sizes, int n_in,
                              void* d_out, int out_size) {
    const float* x    = (const float*)d_in[0];
    const float* zf   = (const float*)d_in[1];
    const int*   nbr  = (const int*)d_in[2];
    const float* w1   = (const float*)d_in[3];
    const float* g1   = (const float*)d_in[4];
    const float* b1   = (const float*)d_in[5];
    const float* m1   = (const float*)d_in[6];
    const float* v1   = (const float*)d_in[7];
    const float* w2   = (const float*)d_in[8];
    const float* mw   = (const float*)d_in[9];
    const float* mb   = (const float*)d_in[10];
    const float* mg   = (const float*)d_in[11];
    const float* mbt  = (const float*)d_in[12];
    const float* mm   = (const float*)d_in[13];
    const float* mv   = (const float*)d_in[14];
    float* out = (float*)d_out;

    size_t off2 = (size_t)out_size - (size_t)N_NODES * FOUT;

    int prepGrid = N_NODES / 256 + (KNBR * FOUT * 8 + 255) / 256;
    prep_kernel<<<prepGrid, 256>>>(x, w2);
    stage1_kernel<<<N_NODES / 512, 256>>>(nbr, w1, g1, b1, m1, v1);

    cudaFuncSetAttribute(stage2_mma,
                         cudaFuncAttributeMaxDynamicSharedMemorySize, SMEM_TOT);
    stage2_mma<<<N_NODES / 256, 256, SMEM_TOT>>>(
        nbr, zf, mw, mb, mg, mbt, mm, mv, out, off2);
}